// round 2
// baseline (speedup 1.0000x reference)
#include <cuda_runtime.h>
#include <math.h>

#define BATCH   8192
#define P_DIM   512
#define DM      256     // D_MODEL
#define DI      512     // D_INNER = 2*D_MODEL
#define DS      16      // D_STATE
#define DTR     16      // DT_RANK
#define ADIM    64

// ---------------- scratch (device globals; no allocation allowed) ----------------
__device__ float g_x   [BATCH * DM];       // perception @ W_in^T + b
__device__ float g_U   [BATCH * DI];       // silu(conv(u))
__device__ float g_Zs  [BATCH * DI];       // silu(z)
__device__ float g_xdbl[BATCH * 48];       // u @ x_proj^T
__device__ float g_Y   [BATCH * DI];       // ssm output * silu(z)
__device__ float g_h   [BATCH * DM];       // y @ out_proj^T

__device__ __forceinline__ float siluf(float x) { return x / (1.f + __expf(-x)); }
__device__ __forceinline__ float softplusf(float x) {
    return (x > 20.f) ? x : log1pf(__expf(x));
}

// ---------------- generic NT SGEMM: C[m,n] = sum_k A[m,k] * W[n,k] ----------------
// BM=128, BN=64, BK=16, 256 threads, 8x4 per thread. Dims must divide tiles.
// EPI: 0=+bias(e0)  1=mamba-in split(conv+silu -> C / silu -> e2)
//      2=plain      3=tanh head(+e0 -> e2)  4=clip head(+e0 -> e2)
template<int EPI>
__global__ void __launch_bounds__(256)
sgemm_nt(const float* __restrict__ A, const float* __restrict__ W,
         float* __restrict__ C, int M, int N, int K,
         const float* __restrict__ e0, const float* __restrict__ e1,
         float* __restrict__ e2)
{
    constexpr int BM = 128, BN = 64, BK = 16, TM = 8, TN = 4;
    __shared__ float As[BK][BM + 1];
    __shared__ float Bs[BK][BN + 1];

    const int tid = threadIdx.x;
    const int m0 = blockIdx.y * BM;
    const int n0 = blockIdx.x * BN;
    const int tx = tid & 15;        // N direction
    const int ty = tid >> 4;        // M direction

    float acc[TM][TN];
#pragma unroll
    for (int i = 0; i < TM; i++)
#pragma unroll
        for (int j = 0; j < TN; j++) acc[i][j] = 0.f;

    for (int k0 = 0; k0 < K; k0 += BK) {
        // A tile: 128x16 = 512 float4 loads, 2 per thread, transposed into As
#pragma unroll
        for (int it = 0; it < 2; it++) {
            int idx = tid + it * 256;           // 0..511
            int m   = idx >> 2;                 // 0..127
            int kc  = (idx & 3) << 2;           // 0,4,8,12
            float4 v = *reinterpret_cast<const float4*>(
                A + (size_t)(m0 + m) * K + k0 + kc);
            As[kc + 0][m] = v.x; As[kc + 1][m] = v.y;
            As[kc + 2][m] = v.z; As[kc + 3][m] = v.w;
        }
        // W tile: 64x16 = 256 float4 loads, 1 per thread
        {
            int n  = tid >> 2;                  // 0..63
            int kc = (tid & 3) << 2;
            float4 v = *reinterpret_cast<const float4*>(
                W + (size_t)(n0 + n) * K + k0 + kc);
            Bs[kc + 0][n] = v.x; Bs[kc + 1][n] = v.y;
            Bs[kc + 2][n] = v.z; Bs[kc + 3][n] = v.w;
        }
        __syncthreads();

#pragma unroll
        for (int k = 0; k < BK; k++) {
            float ra[TM], rb[TN];
#pragma unroll
            for (int i = 0; i < TM; i++) ra[i] = As[k][ty * TM + i];
#pragma unroll
            for (int j = 0; j < TN; j++) rb[j] = Bs[k][tx * TN + j];
#pragma unroll
            for (int i = 0; i < TM; i++)
#pragma unroll
                for (int j = 0; j < TN; j++)
                    acc[i][j] = fmaf(ra[i], rb[j], acc[i][j]);
        }
        __syncthreads();
    }

#pragma unroll
    for (int i = 0; i < TM; i++) {
        const int m = m0 + ty * TM + i;
#pragma unroll
        for (int j = 0; j < TN; j++) {
            const int n = n0 + tx * TN + j;
            float v = acc[i][j];
            if (EPI == 0) {                       // + bias
                C[(size_t)m * N + n] = v + e0[n];
            } else if (EPI == 1) {                // mamba input: u -> conv+silu, z -> silu
                if (n < DI) {
                    float t = v * e0[n * 4 + 3] + e1[n];   // conv_w[n][3], conv_b[n]
                    C[(size_t)m * DI + n] = siluf(t);
                } else {
                    e2[(size_t)m * DI + (n - DI)] = siluf(v);
                }
            } else if (EPI == 2) {                // plain
                C[(size_t)m * N + n] = v;
            } else if (EPI == 3) {                // mu head
                e2[(size_t)m * ADIM + n] = tanhf(v + e0[n]);
            } else {                              // log_std head
                float t = v + e0[n];
                t = fminf(fmaxf(t, -5.f), 2.f);
                e2[(size_t)m * ADIM + n] = t;
            }
        }
    }
}

// ---------------- x_dbl GEMM: M=8192, N=48, K=512 ----------------
__global__ void __launch_bounds__(256)
gemm_xdbl(const float* __restrict__ A, const float* __restrict__ W,
          float* __restrict__ C)
{
    constexpr int BM = 64, BK = 16, TM = 4, TN = 3;
    __shared__ float As[BK][BM + 1];
    __shared__ float Bs[BK][48 + 1];

    const int tid = threadIdx.x;
    const int m0 = blockIdx.x * BM;
    const int tx = tid & 15, ty = tid >> 4;

    float acc[TM][TN];
#pragma unroll
    for (int i = 0; i < TM; i++)
#pragma unroll
        for (int j = 0; j < TN; j++) acc[i][j] = 0.f;

    for (int k0 = 0; k0 < DI; k0 += BK) {
        {
            int m = tid >> 2, kc = (tid & 3) << 2;
            float4 v = *reinterpret_cast<const float4*>(
                A + (size_t)(m0 + m) * DI + k0 + kc);
            As[kc + 0][m] = v.x; As[kc + 1][m] = v.y;
            As[kc + 2][m] = v.z; As[kc + 3][m] = v.w;
        }
        if (tid < 192) {
            int n = tid >> 2, kc = (tid & 3) << 2;
            float4 v = *reinterpret_cast<const float4*>(
                W + (size_t)n * DI + k0 + kc);
            Bs[kc + 0][n] = v.x; Bs[kc + 1][n] = v.y;
            Bs[kc + 2][n] = v.z; Bs[kc + 3][n] = v.w;
        }
        __syncthreads();
#pragma unroll
        for (int k = 0; k < BK; k++) {
            float ra[TM], rb[TN];
#pragma unroll
            for (int i = 0; i < TM; i++) ra[i] = As[k][ty * TM + i];
#pragma unroll
            for (int j = 0; j < TN; j++) rb[j] = Bs[k][tx * TN + j];
#pragma unroll
            for (int i = 0; i < TM; i++)
#pragma unroll
                for (int j = 0; j < TN; j++)
                    acc[i][j] = fmaf(ra[i], rb[j], acc[i][j]);
        }
        __syncthreads();
    }
#pragma unroll
    for (int i = 0; i < TM; i++)
#pragma unroll
        for (int j = 0; j < TN; j++)
            C[(size_t)(m0 + ty * TM + i) * 48 + tx * TN + j] = acc[i][j];
}

// ---------------- fused SSM pointwise core ----------------
// With L=1 and h0=0:  y = u * (softplus(dt@dtW^T + dtb) * (B.C) + Dskip) * silu(z)
// Block handles 8 batch rows; each thread owns 2 channels of dt_proj_w.
__global__ void __launch_bounds__(256)
mamba_pointwise(const float* __restrict__ xdbl, const float* __restrict__ dt_w,
                const float* __restrict__ dt_b, const float* __restrict__ Dskip,
                const float* __restrict__ U, const float* __restrict__ Zs,
                float* __restrict__ Y)
{
    constexpr int NB = 8;
    __shared__ float s_xd[NB][48];
    __shared__ float s_bc[NB];
    const int b0 = blockIdx.x * NB;
    const int tid = threadIdx.x;

    for (int i = tid; i < NB * 48; i += 256)
        s_xd[i / 48][i % 48] = xdbl[(size_t)(b0 + i / 48) * 48 + (i % 48)];
    __syncthreads();

    if (tid < NB) {
        float s = 0.f;
#pragma unroll
        for (int n = 0; n < DS; n++) s += s_xd[tid][16 + n] * s_xd[tid][32 + n];
        s_bc[tid] = s;
    }
    __syncthreads();

#pragma unroll
    for (int dd = 0; dd < DI / 256; dd++) {
        const int d = tid + dd * 256;
        const float4 w0 = *reinterpret_cast<const float4*>(dt_w + d * 16 + 0);
        const float4 w1 = *reinterpret_cast<const float4*>(dt_w + d * 16 + 4);
        const float4 w2 = *reinterpret_cast<const float4*>(dt_w + d * 16 + 8);
        const float4 w3 = *reinterpret_cast<const float4*>(dt_w + d * 16 + 12);
        const float bias = dt_b[d];
        const float dsk  = Dskip[d];
#pragma unroll
        for (int bb = 0; bb < NB; bb++) {
            const int b = b0 + bb;
            const float* xd = s_xd[bb];
            float a = bias;
            a = fmaf(w0.x, xd[0],  a); a = fmaf(w0.y, xd[1],  a);
            a = fmaf(w0.z, xd[2],  a); a = fmaf(w0.w, xd[3],  a);
            a = fmaf(w1.x, xd[4],  a); a = fmaf(w1.y, xd[5],  a);
            a = fmaf(w1.z, xd[6],  a); a = fmaf(w1.w, xd[7],  a);
            a = fmaf(w2.x, xd[8],  a); a = fmaf(w2.y, xd[9],  a);
            a = fmaf(w2.z, xd[10], a); a = fmaf(w2.w, xd[11], a);
            a = fmaf(w3.x, xd[12], a); a = fmaf(w3.y, xd[13], a);
            a = fmaf(w3.z, xd[14], a); a = fmaf(w3.w, xd[15], a);
            const float delta = softplusf(a);
            const float u = U[(size_t)b * DI + d];
            const float y = u * fmaf(delta, s_bc[bb], dsk) * Zs[(size_t)b * DI + d];
            Y[(size_t)b * DI + d] = y;
        }
    }
}

// ---------------- launch ----------------
extern "C" void kernel_launch(void* const* d_in, const int* in_sizes, int n_in,
                              void* d_out, int out_size)
{
    const float* perception = (const float*)d_in[0];
    const float* W_in       = (const float*)d_in[1];
    const float* b_in       = (const float*)d_in[2];
    const float* mu_w       = (const float*)d_in[3];
    const float* mu_b       = (const float*)d_in[4];
    const float* ls_w       = (const float*)d_in[5];
    const float* ls_b       = (const float*)d_in[6];
    const float* in_proj_w  = (const float*)d_in[7];
    const float* conv_w     = (const float*)d_in[8];
    const float* conv_b     = (const float*)d_in[9];
    const float* x_proj_w   = (const float*)d_in[10];
    const float* dt_proj_w  = (const float*)d_in[11];
    const float* dt_proj_b  = (const float*)d_in[12];
    /* d_in[13] = A_log — dead with L=1, h0=0 */
    const float* Dskip      = (const float*)d_in[14];
    const float* out_proj_w = (const float*)d_in[15];
    float* out = (float*)d_out;

    float *px, *pU, *pZs, *pxd, *pY, *ph;
    cudaGetSymbolAddress((void**)&px,  g_x);
    cudaGetSymbolAddress((void**)&pU,  g_U);
    cudaGetSymbolAddress((void**)&pZs, g_Zs);
    cudaGetSymbolAddress((void**)&pxd, g_xdbl);
    cudaGetSymbolAddress((void**)&pY,  g_Y);
    cudaGetSymbolAddress((void**)&ph,  g_h);

    // 1) x = perception @ W_in^T + b_in        (8192 x 256, K=512)
    sgemm_nt<0><<<dim3(DM / 64, BATCH / 128), 256>>>(
        perception, W_in, px, BATCH, DM, P_DIM, b_in, nullptr, nullptr);

    // 2) xz = x @ in_proj^T (N=1024); u -> conv+silu -> g_U; z -> silu -> g_Zs
    sgemm_nt<1><<<dim3(2 * DI / 64, BATCH / 128), 256>>>(
        px, in_proj_w, pU, BATCH, 2 * DI, DM, conv_w, conv_b, pZs);

    // 3) x_dbl = U @ x_proj^T                  (8192 x 48, K=512)
    gemm_xdbl<<<BATCH / 64, 256>>>(pU, x_proj_w, pxd);

    // 4) fused delta/BC/gating -> Y
    mamba_pointwise<<<BATCH / 8, 256>>>(pxd, dt_proj_w, dt_proj_b, Dskip,
                                        pU, pZs, pY);

    // 5) h = Y @ out_proj^T                    (8192 x 256, K=512)
    sgemm_nt<2><<<dim3(DM / 64, BATCH / 128), 256>>>(
        pY, out_proj_w, ph, BATCH, DM, DI, nullptr, nullptr, nullptr);

    // 6) heads: mu = tanh(h@mu_w^T + mu_b); ls = clip(h@ls_w^T + ls_b)
    sgemm_nt<3><<<dim3(1, BATCH / 128), 256>>>(
        ph, mu_w, nullptr, BATCH, ADIM, DM, mu_b, nullptr, out);
    sgemm_nt<4><<<dim3(1, BATCH / 128), 256>>>(
        ph, ls_w, nullptr, BATCH, ADIM, DM, ls_b, nullptr,
        out + (size_t)BATCH * ADIM);
}

// round 5
// speedup vs baseline: 1.8639x; 1.8639x over previous
#include <cuda_runtime.h>
#include <cuda_bf16.h>
#include <math.h>
#include <stdint.h>

#define BATCH   8192
#define P_DIM   512
#define DM      256     // D_MODEL
#define DI      512     // D_INNER
#define DS      16
#define ADIM    64

// ---------------- scratch (device globals) ----------------
__device__ float g_x   [BATCH * DM];
__device__ float g_U   [BATCH * DI];
__device__ float g_Zs  [BATCH * DI];
__device__ float g_xdbl[BATCH * 48];
__device__ float g_Y   [BATCH * DI];
__device__ float g_h   [BATCH * DM];
__device__ float g_hw  [128 * DM];      // concat(mu_w, ls_w)
__device__ float g_hb  [128];           // concat(mu_b, ls_b)
__device__ float g_xp  [64 * DI];       // x_proj_w zero-padded 48->64 rows

__device__ __forceinline__ float siluf(float x) { return x / (1.f + __expf(-x)); }
__device__ __forceinline__ float softplusf(float x) {
    return (x > 20.f) ? x : log1pf(__expf(x));
}

__device__ __forceinline__ uint32_t smem_u32(const void* p) {
    uint32_t a;
    asm("{ .reg .u64 t; cvta.to.shared.u64 t, %1; cvt.u32.u64 %0, t; }"
        : "=r"(a) : "l"(p));
    return a;
}
__device__ __forceinline__ void ldsm4(uint32_t addr, uint32_t r[4]) {
    asm volatile("ldmatrix.sync.aligned.m8n8.x4.shared.b16 {%0,%1,%2,%3}, [%4];"
                 : "=r"(r[0]), "=r"(r[1]), "=r"(r[2]), "=r"(r[3]) : "r"(addr));
}
__device__ __forceinline__ void mma16816(float c[4], const uint32_t a[4],
                                         uint32_t b0, uint32_t b1) {
    asm volatile(
        "mma.sync.aligned.m16n8k16.row.col.f32.bf16.bf16.f32 "
        "{%0,%1,%2,%3}, {%4,%5,%6,%7}, {%8,%9}, {%0,%1,%2,%3};"
        : "+f"(c[0]), "+f"(c[1]), "+f"(c[2]), "+f"(c[3])
        : "r"(a[0]), "r"(a[1]), "r"(a[2]), "r"(a[3]), "r"(b0), "r"(b1));
}
// split two floats into packed bf16 hi/lo planes
__device__ __forceinline__ void split2(float x, float y, uint32_t& hi, uint32_t& lo) {
    __nv_bfloat16 hx = __float2bfloat16(x), hy = __float2bfloat16(y);
    float rx = x - __bfloat162float(hx);
    float ry = y - __bfloat162float(hy);
    __nv_bfloat16 lx = __float2bfloat16(rx), ly = __float2bfloat16(ry);
    hi = (uint32_t)__bfloat16_as_ushort(hx) | ((uint32_t)__bfloat16_as_ushort(hy) << 16);
    lo = (uint32_t)__bfloat16_as_ushort(lx) | ((uint32_t)__bfloat16_as_ushort(ly) << 16);
}

// ============ bf16x3 tensor-core NT GEMM: C[m,n] = sum_k A[m,k] * W[n,k] ============
// Tile 128(M) x 64(N) x 32(K). 256 threads = 8 warps (4m x 2n), 32x32 per warp.
// smem rows padded to 80B -> conflict-free ldmatrix.
// EPI: 0 +bias->C | 1 in_proj split | 2 plain->C | 3 dual head | 4 xdbl (n<48, ldc=48)
template<int EPI>
__global__ void __launch_bounds__(256)
mma_gemm(const float* __restrict__ A, const float* __restrict__ W,
         float* __restrict__ C, int K,
         const float* __restrict__ e0, const float* __restrict__ e1,
         float* __restrict__ e2)
{
    constexpr int BM = 128, BN = 64, LDS = 80;
    __shared__ __align__(16) uint8_t sA[2][BM * LDS];
    __shared__ __align__(16) uint8_t sB[2][BN * LDS];

    const int tid  = threadIdx.x;
    const int lane = tid & 31, wid = tid >> 5;
    const int wm = wid & 3, wn = wid >> 2;
    const int m0 = blockIdx.y * BM, n0 = blockIdx.x * BN;

    const uint32_t aA0 = smem_u32(sA[0]), aA1 = smem_u32(sA[1]);
    const uint32_t aB0 = smem_u32(sB[0]), aB1 = smem_u32(sB[1]);

    float acc[2][4][4];
#pragma unroll
    for (int i = 0; i < 2; i++)
#pragma unroll
        for (int j = 0; j < 4; j++)
#pragma unroll
            for (int l = 0; l < 4; l++) acc[i][j][l] = 0.f;

    const int lr  = lane & 7, sub = lane >> 3;

    for (int k0 = 0; k0 < K; k0 += 32) {
        // ---- stage A chunk: 128 rows x 8 float4 ----
#pragma unroll
        for (int it = 0; it < 4; ++it) {
            const int idx = tid + it * 256;
            const int r = idx >> 3, c4 = (idx & 7) << 2;
            const float4 v = *reinterpret_cast<const float4*>(
                A + (size_t)(m0 + r) * K + k0 + c4);
            uint32_t h0, l0, h1, l1;
            split2(v.x, v.y, h0, l0);
            split2(v.z, v.w, h1, l1);
            const uint32_t off = (uint32_t)(r * LDS + c4 * 2);
            asm volatile("st.shared.v2.b32 [%0], {%1,%2};" ::
                "r"(aA0 + off), "r"(h0), "r"(h1) : "memory");
            asm volatile("st.shared.v2.b32 [%0], {%1,%2};" ::
                "r"(aA1 + off), "r"(l0), "r"(l1) : "memory");
        }
        // ---- stage B chunk: 64 rows x 8 float4 ----
#pragma unroll
        for (int it = 0; it < 2; ++it) {
            const int idx = tid + it * 256;
            const int r = idx >> 3, c4 = (idx & 7) << 2;
            const float4 v = *reinterpret_cast<const float4*>(
                W + (size_t)(n0 + r) * K + k0 + c4);
            uint32_t h0, l0, h1, l1;
            split2(v.x, v.y, h0, l0);
            split2(v.z, v.w, h1, l1);
            const uint32_t off = (uint32_t)(r * LDS + c4 * 2);
            asm volatile("st.shared.v2.b32 [%0], {%1,%2};" ::
                "r"(aB0 + off), "r"(h0), "r"(h1) : "memory");
            asm volatile("st.shared.v2.b32 [%0], {%1,%2};" ::
                "r"(aB1 + off), "r"(l0), "r"(l1) : "memory");
        }
        __syncthreads();

#pragma unroll
        for (int ks = 0; ks < 2; ++ks) {
            const int kb = ks * 32;                  // byte offset of 16-col group
            uint32_t Ah[2][4], Al[2][4];
            {
                const int rowoff = ((sub & 1) << 3) + lr;
                const int kboff  = kb + ((sub >> 1) << 4);
#pragma unroll
                for (int mt = 0; mt < 2; ++mt) {
                    const uint32_t off =
                        (uint32_t)((wm * 32 + mt * 16 + rowoff) * LDS + kboff);
                    ldsm4(aA0 + off, Ah[mt]);
                    ldsm4(aA1 + off, Al[mt]);
                }
            }
            uint32_t Bh[2][4], Bl[2][4];
            {
                const int nrow  = ((sub >> 1) << 3) + lr;
                const int kboff = kb + ((sub & 1) << 4);
#pragma unroll
                for (int np = 0; np < 2; ++np) {
                    const uint32_t off =
                        (uint32_t)((wn * 32 + np * 16 + nrow) * LDS + kboff);
                    ldsm4(aB0 + off, Bh[np]);
                    ldsm4(aB1 + off, Bl[np]);
                }
            }
#pragma unroll
            for (int mt = 0; mt < 2; ++mt)
#pragma unroll
                for (int nt = 0; nt < 4; ++nt) {
                    const uint32_t bh0 = Bh[nt >> 1][(nt & 1) * 2];
                    const uint32_t bh1 = Bh[nt >> 1][(nt & 1) * 2 + 1];
                    const uint32_t bl0 = Bl[nt >> 1][(nt & 1) * 2];
                    const uint32_t bl1 = Bl[nt >> 1][(nt & 1) * 2 + 1];
                    mma16816(acc[mt][nt], Ah[mt], bh0, bh1);
                    mma16816(acc[mt][nt], Ah[mt], bl0, bl1);
                    mma16816(acc[mt][nt], Al[mt], bh0, bh1);
                }
        }
        __syncthreads();
    }

    // ---- epilogue ----
    const int tg = lane >> 2, tc = lane & 3;
#pragma unroll
    for (int mt = 0; mt < 2; ++mt) {
#pragma unroll
        for (int half = 0; half < 2; ++half) {
            const int m = m0 + wm * 32 + mt * 16 + tg + half * 8;
#pragma unroll
            for (int nt = 0; nt < 4; ++nt) {
                const int n = n0 + wn * 32 + nt * 8 + tc * 2;
                float v0 = acc[mt][nt][half * 2 + 0];
                float v1 = acc[mt][nt][half * 2 + 1];
                if (EPI == 0) {
                    v0 += e0[n]; v1 += e0[n + 1];
                    *reinterpret_cast<float2*>(C + (size_t)m * DM + n) =
                        make_float2(v0, v1);
                } else if (EPI == 1) {
                    if (n < DI) {
                        v0 = siluf(v0 * e0[n * 4 + 3] + e1[n]);
                        v1 = siluf(v1 * e0[(n + 1) * 4 + 3] + e1[n + 1]);
                        *reinterpret_cast<float2*>(C + (size_t)m * DI + n) =
                            make_float2(v0, v1);
                    } else {
                        *reinterpret_cast<float2*>(e2 + (size_t)m * DI + (n - DI)) =
                            make_float2(siluf(v0), siluf(v1));
                    }
                } else if (EPI == 2) {
                    *reinterpret_cast<float2*>(C + (size_t)m * DM + n) =
                        make_float2(v0, v1);
                } else if (EPI == 3) {
                    v0 += e0[n]; v1 += e0[n + 1];
                    if (n < ADIM) {
                        *reinterpret_cast<float2*>(e2 + (size_t)m * ADIM + n) =
                            make_float2(tanhf(v0), tanhf(v1));
                    } else {
                        v0 = fminf(fmaxf(v0, -5.f), 2.f);
                        v1 = fminf(fmaxf(v1, -5.f), 2.f);
                        *reinterpret_cast<float2*>(
                            e2 + (size_t)BATCH * ADIM + (size_t)m * ADIM + (n - ADIM)) =
                            make_float2(v0, v1);
                    }
                } else {                                  // EPI 4: xdbl, ldc=48
                    if (n < 48)
                        *reinterpret_cast<float2*>(C + (size_t)m * 48 + n) =
                            make_float2(v0, v1);
                }
            }
        }
    }
}

// ---------------- fused SSM pointwise ----------------
// L=1, h0=0:  Y = u * (softplus(dt@dtW^T + dtb) * (B.C) + Dskip) * silu(z)
__global__ void __launch_bounds__(256)
mamba_pointwise(const float* __restrict__ xdbl, const float* __restrict__ dt_w,
                const float* __restrict__ dt_b, const float* __restrict__ Dskip,
                const float* __restrict__ U, const float* __restrict__ Zs,
                float* __restrict__ Y)
{
    constexpr int NB = 16;
    __shared__ float s_xd[NB][48];
    __shared__ float s_bc[NB];
    const int b0 = blockIdx.x * NB;
    const int tid = threadIdx.x;

    for (int i = tid; i < NB * 48; i += 256)
        s_xd[i / 48][i % 48] = xdbl[(size_t)(b0 + i / 48) * 48 + (i % 48)];
    __syncthreads();
    if (tid < NB) {
        float s = 0.f;
#pragma unroll
        for (int n = 0; n < DS; n++) s += s_xd[tid][16 + n] * s_xd[tid][32 + n];
        s_bc[tid] = s;
    }
    __syncthreads();

#pragma unroll 1
    for (int dd = 0; dd < DI / 256; dd++) {
        const int d = tid + dd * 256;
        const float4 w0 = *reinterpret_cast<const float4*>(dt_w + d * 16 + 0);
        const float4 w1 = *reinterpret_cast<const float4*>(dt_w + d * 16 + 4);
        const float4 w2 = *reinterpret_cast<const float4*>(dt_w + d * 16 + 8);
        const float4 w3 = *reinterpret_cast<const float4*>(dt_w + d * 16 + 12);
        const float bias = dt_b[d];
        const float dsk  = Dskip[d];
#pragma unroll
        for (int bb = 0; bb < NB; bb++) {
            const int b = b0 + bb;
            const float* xd = s_xd[bb];
            float a = bias;
            a = fmaf(w0.x, xd[0],  a); a = fmaf(w0.y, xd[1],  a);
            a = fmaf(w0.z, xd[2],  a); a = fmaf(w0.w, xd[3],  a);
            a = fmaf(w1.x, xd[4],  a); a = fmaf(w1.y, xd[5],  a);
            a = fmaf(w1.z, xd[6],  a); a = fmaf(w1.w, xd[7],  a);
            a = fmaf(w2.x, xd[8],  a); a = fmaf(w2.y, xd[9],  a);
            a = fmaf(w2.z, xd[10], a); a = fmaf(w2.w, xd[11], a);
            a = fmaf(w3.x, xd[12], a); a = fmaf(w3.y, xd[13], a);
            a = fmaf(w3.z, xd[14], a); a = fmaf(w3.w, xd[15], a);
            const float delta = softplusf(a);
            const float u = U[(size_t)b * DI + d];
            Y[(size_t)b * DI + d] = u * fmaf(delta, s_bc[bb], dsk) * Zs[(size_t)b * DI + d];
        }
    }
}

// ---------------- prep: concat heads + pad x_proj ----------------
__global__ void prep_weights(const float* __restrict__ mu_w, const float* __restrict__ ls_w,
                             const float* __restrict__ mu_b, const float* __restrict__ ls_b,
                             const float* __restrict__ x_proj_w,
                             float* __restrict__ hw, float* __restrict__ hb,
                             float* __restrict__ xp)
{
    const int i = blockIdx.x * 256 + threadIdx.x;       // 0..32767
    hw[i] = (i < ADIM * DM) ? mu_w[i] : ls_w[i - ADIM * DM];
    xp[i] = (i < 48 * DI) ? x_proj_w[i] : 0.f;
    if (i < ADIM) hb[i] = mu_b[i];
    else if (i < 2 * ADIM) hb[i] = ls_b[i - ADIM];
}

// ---------------- launch ----------------
extern "C" void kernel_launch(void* const* d_in, const int* in_sizes, int n_in,
                              void* d_out, int out_size)
{
    const float* perception = (const float*)d_in[0];
    const float* W_in       = (const float*)d_in[1];
    const float* b_in       = (const float*)d_in[2];
    const float* mu_w       = (const float*)d_in[3];
    const float* mu_b       = (const float*)d_in[4];
    const float* ls_w       = (const float*)d_in[5];
    const float* ls_b       = (const float*)d_in[6];
    const float* in_proj_w  = (const float*)d_in[7];
    const float* conv_w     = (const float*)d_in[8];
    const float* conv_b     = (const float*)d_in[9];
    const float* x_proj_w   = (const float*)d_in[10];
    const float* dt_proj_w  = (const float*)d_in[11];
    const float* dt_proj_b  = (const float*)d_in[12];
    const float* Dskip      = (const float*)d_in[14];
    const float* out_proj_w = (const float*)d_in[15];
    float* out = (float*)d_out;

    float *px, *pU, *pZs, *pxd, *pY, *ph, *phw, *phb, *pxp;
    cudaGetSymbolAddress((void**)&px,  g_x);
    cudaGetSymbolAddress((void**)&pU,  g_U);
    cudaGetSymbolAddress((void**)&pZs, g_Zs);
    cudaGetSymbolAddress((void**)&pxd, g_xdbl);
    cudaGetSymbolAddress((void**)&pY,  g_Y);
    cudaGetSymbolAddress((void**)&ph,  g_h);
    cudaGetSymbolAddress((void**)&phw, g_hw);
    cudaGetSymbolAddress((void**)&phb, g_hb);
    cudaGetSymbolAddress((void**)&pxp, g_xp);

    // 0) weight prep (inputs only)
    prep_weights<<<128, 256>>>(mu_w, ls_w, mu_b, ls_b, x_proj_w, phw, phb, pxp);

    // 1) x = perception @ W_in^T + b_in           (8192 x 256, K=512)
    mma_gemm<0><<<dim3(DM / 64, BATCH / 128), 256>>>(
        perception, W_in, px, P_DIM, b_in, nullptr, nullptr);

    // 2) xz = x @ in_proj^T (N=1024) -> U (conv+silu) / Zs (silu)   K=256
    mma_gemm<1><<<dim3(2 * DI / 64, BATCH / 128), 256>>>(
        px, in_proj_w, pU, DM, conv_w, conv_b, pZs);

    // 3) x_dbl = U @ xp^T (N=64 padded, store n<48)  K=512
    mma_gemm<4><<<dim3(1, BATCH / 128), 256>>>(
        pU, pxp, pxd, DI, nullptr, nullptr, nullptr);

    // 4) fused delta/BC/gating -> Y
    mamba_pointwise<<<BATCH / 16, 256>>>(pxd, dt_proj_w, dt_proj_b, Dskip, pU, pZs, pY);

    // 5) h = Y @ out_proj^T                       (8192 x 256, K=512)
    mma_gemm<2><<<dim3(DM / 64, BATCH / 128), 256>>>(
        pY, out_proj_w, ph, DI, nullptr, nullptr, nullptr);

    // 6) heads: [mu | log_std] = h @ [mu_w;ls_w]^T (8192 x 128, K=256)
    mma_gemm<3><<<dim3(2, BATCH / 128), 256>>>(
        ph, phw, nullptr, DM, phb, nullptr, out);
}

// round 6
// speedup vs baseline: 2.0463x; 1.0979x over previous
#include <cuda_runtime.h>
#include <cuda_bf16.h>
#include <math.h>
#include <stdint.h>

#define BATCH   8192
#define P_DIM   512
#define DM      256     // D_MODEL
#define DI      512     // D_INNER
#define DS      16
#define ADIM    64

typedef __nv_bfloat16 bf16;

// ---------------- fp32 scratch ----------------
__device__ float g_U  [BATCH * DI];
__device__ float g_Zs [BATCH * DI];
__device__ float g_xd [2 * BATCH * 48];        // split-K partials
__device__ float g_hb [128];

// ---------------- bf16 hi/lo planes (activations) ----------------
__device__ __align__(256) bf16 g_ph[BATCH * P_DIM], g_pl[BATCH * P_DIM];
__device__ __align__(256) bf16 g_xh[BATCH * DM],    g_xl[BATCH * DM];
__device__ __align__(256) bf16 g_Uh[BATCH * DI],    g_Ul[BATCH * DI];
__device__ __align__(256) bf16 g_Yh[BATCH * DI],    g_Yl[BATCH * DI];
__device__ __align__(256) bf16 g_hh[BATCH * DM],    g_hl[BATCH * DM];

// ---------------- bf16 hi/lo planes (weights) ----------------
__device__ __align__(256) bf16 g_Winh[DM * P_DIM],   g_Winl[DM * P_DIM];
__device__ __align__(256) bf16 g_iph [2 * DI * DM],  g_ipl [2 * DI * DM];
__device__ __align__(256) bf16 g_oph [DM * DI],      g_opl [DM * DI];
__device__ __align__(256) bf16 g_xph [64 * DI],      g_xpl [64 * DI];
__device__ __align__(256) bf16 g_hwh [128 * DM],     g_hwl [128 * DM];

__device__ __forceinline__ float siluf(float x) { return x / (1.f + __expf(-x)); }
__device__ __forceinline__ float softplusf(float x) {
    return (x > 20.f) ? x : log1pf(__expf(x));
}
__device__ __forceinline__ uint32_t smem_u32(const void* p) {
    uint32_t a;
    asm("{ .reg .u64 t; cvta.to.shared.u64 t, %1; cvt.u32.u64 %0, t; }"
        : "=r"(a) : "l"(p));
    return a;
}
__device__ __forceinline__ void ldsm4(uint32_t addr, uint32_t r[4]) {
    asm volatile("ldmatrix.sync.aligned.m8n8.x4.shared.b16 {%0,%1,%2,%3}, [%4];"
                 : "=r"(r[0]), "=r"(r[1]), "=r"(r[2]), "=r"(r[3]) : "r"(addr));
}
__device__ __forceinline__ void mma16816(float c[4], const uint32_t a[4],
                                         uint32_t b0, uint32_t b1) {
    asm volatile(
        "mma.sync.aligned.m16n8k16.row.col.f32.bf16.bf16.f32 "
        "{%0,%1,%2,%3}, {%4,%5,%6,%7}, {%8,%9}, {%0,%1,%2,%3};"
        : "+f"(c[0]), "+f"(c[1]), "+f"(c[2]), "+f"(c[3])
        : "r"(a[0]), "r"(a[1]), "r"(a[2]), "r"(a[3]), "r"(b0), "r"(b1));
}
#define CP_ASYNC16(dst, src) \
    asm volatile("cp.async.cg.shared.global [%0], [%1], 16;" :: "r"(dst), "l"(src))
#define CP_COMMIT()  asm volatile("cp.async.commit_group;" ::: "memory")
#define CP_WAIT0()   asm volatile("cp.async.wait_group 0;" ::: "memory")

// split float pair -> bf16 hi/lo planes at offset
__device__ __forceinline__ void wsplit2(bf16* H, bf16* L, size_t off,
                                        float v0, float v1) {
    bf16 h0 = __float2bfloat16(v0), h1 = __float2bfloat16(v1);
    bf16 l0 = __float2bfloat16(v0 - __bfloat162float(h0));
    bf16 l1 = __float2bfloat16(v1 - __bfloat162float(h1));
    *reinterpret_cast<__nv_bfloat162*>(H + off) = __halves2bfloat162(h0, h1);
    *reinterpret_cast<__nv_bfloat162*>(L + off) = __halves2bfloat162(l0, l1);
}
__device__ __forceinline__ void wsplit1(bf16* H, bf16* L, size_t off, float v) {
    bf16 h = __float2bfloat16(v);
    H[off] = h;
    L[off] = __float2bfloat16(v - __bfloat162float(h));
}

// ============ bf16x3 tensor GEMM, cp.async double-buffered ============
// Tile 128(M) x 64(N) x 32(K). 256 thr = 8 warps (4m x 2n), 32x32/warp.
// smem/buffer: Ah 10240 | Al 10240 | Bh 5120 | Bl 5120 = 30720; x2 = 61440.
// EPI: 0 +bias -> x planes | 1 in_proj split | 2 -> h planes | 3 heads -> out
//      4 xdbl partial (grid.z = split, n<48)
#define GSMEM 61440
#define BUFSZ 30720

template<int EPI>
__global__ void __launch_bounds__(256)
mma_gemm(const bf16* __restrict__ Ah, const bf16* __restrict__ Al,
         const bf16* __restrict__ Bh, const bf16* __restrict__ Bl,
         int K, int lda,
         float* __restrict__ C, const float* __restrict__ e0,
         const float* __restrict__ e1, float* __restrict__ e2,
         bf16* __restrict__ Ch, bf16* __restrict__ Cl)
{
    constexpr int LDS = 80;
    extern __shared__ __align__(16) uint8_t dsm[];
    const uint32_t sb = smem_u32(dsm);

    const int tid  = threadIdx.x;
    const int lane = tid & 31, wid = tid >> 5;
    const int wm = wid & 3, wn = wid >> 2;
    const int m0 = blockIdx.y * 128, n0 = blockIdx.x * 64;
    const int kOff = blockIdx.z * K;

    const int lr = lane & 7, sub = lane >> 3;

    float acc[2][4][4];
#pragma unroll
    for (int i = 0; i < 2; i++)
#pragma unroll
        for (int j = 0; j < 4; j++)
#pragma unroll
            for (int l = 0; l < 4; l++) acc[i][j][l] = 0.f;

    const int nchunks = K >> 5;

    // ---- copy chunk c into buffer buf ----
    auto copy_chunk = [&](int c, int buf) {
        const int kg = kOff + (c << 5);
        const uint32_t b = sb + buf * BUFSZ;
#pragma unroll
        for (int j = 0; j < 2; ++j) {
            const int idx = tid + j * 256;
            const int row = idx >> 2, cc = idx & 3;
            const size_t go = (size_t)(m0 + row) * lda + kg + cc * 8;
            const uint32_t so = b + row * LDS + cc * 16;
            CP_ASYNC16(so,         Ah + go);
            CP_ASYNC16(so + 10240, Al + go);
        }
        {
            const int row = tid >> 2, cc = tid & 3;
            const size_t go = (size_t)(n0 + row) * lda + kg + cc * 8;
            const uint32_t so = b + 20480 + row * LDS + cc * 16;
            CP_ASYNC16(so,        Bh + go);
            CP_ASYNC16(so + 5120, Bl + go);
        }
        CP_COMMIT();
    };

    copy_chunk(0, 0);

    for (int c = 0; c < nchunks; ++c) {
        CP_WAIT0();
        __syncthreads();
        if (c + 1 < nchunks) copy_chunk(c + 1, (c + 1) & 1);

        const uint32_t b   = sb + (c & 1) * BUFSZ;
        const uint32_t aAh = b, aAl = b + 10240;
        const uint32_t aBh = b + 20480, aBl = b + 25600;

#pragma unroll
        for (int ks = 0; ks < 2; ++ks) {
            const int kb = ks * 32;
            uint32_t Afh[2][4], Afl[2][4];
            {
                const int rowoff = ((sub & 1) << 3) + lr;
                const int kboff  = kb + ((sub >> 1) << 4);
#pragma unroll
                for (int mt = 0; mt < 2; ++mt) {
                    const uint32_t off =
                        (uint32_t)((wm * 32 + mt * 16 + rowoff) * LDS + kboff);
                    ldsm4(aAh + off, Afh[mt]);
                    ldsm4(aAl + off, Afl[mt]);
                }
            }
            uint32_t Bfh[2][4], Bfl[2][4];
            {
                const int nrow  = ((sub >> 1) << 3) + lr;
                const int kboff = kb + ((sub & 1) << 4);
#pragma unroll
                for (int np = 0; np < 2; ++np) {
                    const uint32_t off =
                        (uint32_t)((wn * 32 + np * 16 + nrow) * LDS + kboff);
                    ldsm4(aBh + off, Bfh[np]);
                    ldsm4(aBl + off, Bfl[np]);
                }
            }
#pragma unroll
            for (int mt = 0; mt < 2; ++mt)
#pragma unroll
                for (int nt = 0; nt < 4; ++nt) {
                    const uint32_t bh0 = Bfh[nt >> 1][(nt & 1) * 2];
                    const uint32_t bh1 = Bfh[nt >> 1][(nt & 1) * 2 + 1];
                    const uint32_t bl0 = Bfl[nt >> 1][(nt & 1) * 2];
                    const uint32_t bl1 = Bfl[nt >> 1][(nt & 1) * 2 + 1];
                    mma16816(acc[mt][nt], Afh[mt], bh0, bh1);
                    mma16816(acc[mt][nt], Afh[mt], bl0, bl1);
                    mma16816(acc[mt][nt], Afl[mt], bh0, bh1);
                }
        }
    }

    // ---- epilogue ----
    const int tg = lane >> 2, tc = lane & 3;
#pragma unroll
    for (int mt = 0; mt < 2; ++mt) {
#pragma unroll
        for (int half = 0; half < 2; ++half) {
            const int m = m0 + wm * 32 + mt * 16 + tg + half * 8;
#pragma unroll
            for (int nt = 0; nt < 4; ++nt) {
                const int n = n0 + wn * 32 + nt * 8 + tc * 2;
                float v0 = acc[mt][nt][half * 2 + 0];
                float v1 = acc[mt][nt][half * 2 + 1];
                if (EPI == 0) {                      // x: +bias -> planes
                    v0 += e0[n]; v1 += e0[n + 1];
                    wsplit2(Ch, Cl, (size_t)m * DM + n, v0, v1);
                } else if (EPI == 1) {               // in_proj split
                    if (n < DI) {
                        v0 = siluf(v0 * e0[n * 4 + 3] + e1[n]);
                        v1 = siluf(v1 * e0[(n + 1) * 4 + 3] + e1[n + 1]);
                        *reinterpret_cast<float2*>(C + (size_t)m * DI + n) =
                            make_float2(v0, v1);
                        wsplit2(Ch, Cl, (size_t)m * DI + n, v0, v1);
                    } else {
                        *reinterpret_cast<float2*>(e2 + (size_t)m * DI + (n - DI)) =
                            make_float2(siluf(v0), siluf(v1));
                    }
                } else if (EPI == 2) {               // h -> planes
                    wsplit2(Ch, Cl, (size_t)m * DM + n, v0, v1);
                } else if (EPI == 3) {               // heads -> out
                    v0 += e0[n]; v1 += e0[n + 1];
                    if (n < ADIM) {
                        *reinterpret_cast<float2*>(e2 + (size_t)m * ADIM + n) =
                            make_float2(tanhf(v0), tanhf(v1));
                    } else {
                        v0 = fminf(fmaxf(v0, -5.f), 2.f);
                        v1 = fminf(fmaxf(v1, -5.f), 2.f);
                        *reinterpret_cast<float2*>(
                            e2 + (size_t)BATCH * ADIM + (size_t)m * ADIM + (n - ADIM)) =
                            make_float2(v0, v1);
                    }
                } else {                             // EPI 4: xdbl partial
                    if (n < 48)
                        *reinterpret_cast<float2*>(
                            C + (size_t)blockIdx.z * BATCH * 48 + (size_t)m * 48 + n) =
                            make_float2(v0, v1);
                }
            }
        }
    }
}

// ---------------- fused SSM pointwise ----------------
// Y = u * (softplus(dt@dtW^T + dtb) * (B.C) + Dskip) * silu(z)  -> bf16 planes
__global__ void __launch_bounds__(256)
mamba_pointwise(const float* __restrict__ xdbl, const float* __restrict__ dt_w,
                const float* __restrict__ dt_b, const float* __restrict__ Dskip,
                const float* __restrict__ U, const float* __restrict__ Zs,
                bf16* __restrict__ Yh, bf16* __restrict__ Yl)
{
    constexpr int NB = 16;
    __shared__ float s_xd[NB][48];
    __shared__ float s_bc[NB];
    const int b0 = blockIdx.x * NB;
    const int tid = threadIdx.x;

    for (int i = tid; i < NB * 48; i += 256) {
        const size_t off = (size_t)(b0 + i / 48) * 48 + (i % 48);
        s_xd[i / 48][i % 48] = xdbl[off] + xdbl[(size_t)BATCH * 48 + off];
    }
    __syncthreads();
    if (tid < NB) {
        float s = 0.f;
#pragma unroll
        for (int n = 0; n < DS; n++) s += s_xd[tid][16 + n] * s_xd[tid][32 + n];
        s_bc[tid] = s;
    }
    __syncthreads();

#pragma unroll 1
    for (int dd = 0; dd < DI / 256; dd++) {
        const int d = tid + dd * 256;
        const float4 w0 = *reinterpret_cast<const float4*>(dt_w + d * 16 + 0);
        const float4 w1 = *reinterpret_cast<const float4*>(dt_w + d * 16 + 4);
        const float4 w2 = *reinterpret_cast<const float4*>(dt_w + d * 16 + 8);
        const float4 w3 = *reinterpret_cast<const float4*>(dt_w + d * 16 + 12);
        const float bias = dt_b[d];
        const float dsk  = Dskip[d];
#pragma unroll
        for (int bb = 0; bb < NB; bb++) {
            const int b = b0 + bb;
            const float* xd = s_xd[bb];
            float a = bias;
            a = fmaf(w0.x, xd[0],  a); a = fmaf(w0.y, xd[1],  a);
            a = fmaf(w0.z, xd[2],  a); a = fmaf(w0.w, xd[3],  a);
            a = fmaf(w1.x, xd[4],  a); a = fmaf(w1.y, xd[5],  a);
            a = fmaf(w1.z, xd[6],  a); a = fmaf(w1.w, xd[7],  a);
            a = fmaf(w2.x, xd[8],  a); a = fmaf(w2.y, xd[9],  a);
            a = fmaf(w2.z, xd[10], a); a = fmaf(w2.w, xd[11], a);
            a = fmaf(w3.x, xd[12], a); a = fmaf(w3.y, xd[13], a);
            a = fmaf(w3.z, xd[14], a); a = fmaf(w3.w, xd[15], a);
            const float delta = softplusf(a);
            const float u = U[(size_t)b * DI + d];
            const float y = u * fmaf(delta, s_bc[bb], dsk) * Zs[(size_t)b * DI + d];
            wsplit1(Yh, Yl, (size_t)b * DI + d, y);
        }
    }
}

// ---------------- weight prep: split everything into planes ----------------
__global__ void prep(const float* __restrict__ W_in, const float* __restrict__ ip,
                     const float* __restrict__ op,  const float* __restrict__ xp,
                     const float* __restrict__ mu_w, const float* __restrict__ ls_w,
                     const float* __restrict__ mu_b, const float* __restrict__ ls_b,
                     float* __restrict__ hb)
{
    const int i = blockIdx.x * 256 + threadIdx.x;
    if (i < 131072) {
        wsplit1(g_Winh, g_Winl, i, W_in[i]);
    } else if (i < 393216) {
        const int j = i - 131072;
        wsplit1(g_iph, g_ipl, j, ip[j]);
    } else if (i < 524288) {
        const int j = i - 393216;
        wsplit1(g_oph, g_opl, j, op[j]);
    } else if (i < 557056) {
        const int j = i - 524288;                // 64x512 padded; rows>=48 zero
        wsplit1(g_xph, g_xpl, j, (j < 48 * DI) ? xp[j] : 0.f);
    } else if (i < 589824) {
        const int j = i - 557056;                // 128x256 concat
        wsplit1(g_hwh, g_hwl, j, (j < ADIM * DM) ? mu_w[j] : ls_w[j - ADIM * DM]);
    }
    if (i < 128) hb[i] = (i < ADIM) ? mu_b[i] : ls_b[i - ADIM];
}

// ---------------- perception -> planes ----------------
__global__ void conv_perc(const float* __restrict__ src)
{
    const size_t i = ((size_t)blockIdx.x * 256 + threadIdx.x) * 4;
    const float4 v = *reinterpret_cast<const float4*>(src + i);
    wsplit2(g_ph, g_pl, i,     v.x, v.y);
    wsplit2(g_ph, g_pl, i + 2, v.z, v.w);
}

// ---------------- launch ----------------
extern "C" void kernel_launch(void* const* d_in, const int* in_sizes, int n_in,
                              void* d_out, int out_size)
{
    const float* perception = (const float*)d_in[0];
    const float* W_in       = (const float*)d_in[1];
    const float* b_in       = (const float*)d_in[2];
    const float* mu_w       = (const float*)d_in[3];
    const float* mu_b       = (const float*)d_in[4];
    const float* ls_w       = (const float*)d_in[5];
    const float* ls_b       = (const float*)d_in[6];
    const float* in_proj_w  = (const float*)d_in[7];
    const float* conv_w     = (const float*)d_in[8];
    const float* conv_b     = (const float*)d_in[9];
    const float* x_proj_w   = (const float*)d_in[10];
    const float* dt_proj_w  = (const float*)d_in[11];
    const float* dt_proj_b  = (const float*)d_in[12];
    const float* Dskip      = (const float*)d_in[14];
    const float* out_proj_w = (const float*)d_in[15];
    float* out = (float*)d_out;

    float *pU, *pZs, *pxd, *phb;
    cudaGetSymbolAddress((void**)&pU,  g_U);
    cudaGetSymbolAddress((void**)&pZs, g_Zs);
    cudaGetSymbolAddress((void**)&pxd, g_xd);
    cudaGetSymbolAddress((void**)&phb, g_hb);

    bf16 *ph_, *pl_, *xh, *xl, *Uh, *Ul, *Yh, *Yl, *hh, *hl;
    bf16 *Wh, *Wl, *ih, *il, *oh, *ol, *xph_, *xpl_, *hwh, *hwl;
    cudaGetSymbolAddress((void**)&ph_, g_ph);  cudaGetSymbolAddress((void**)&pl_, g_pl);
    cudaGetSymbolAddress((void**)&xh,  g_xh);  cudaGetSymbolAddress((void**)&xl,  g_xl);
    cudaGetSymbolAddress((void**)&Uh,  g_Uh);  cudaGetSymbolAddress((void**)&Ul,  g_Ul);
    cudaGetSymbolAddress((void**)&Yh,  g_Yh);  cudaGetSymbolAddress((void**)&Yl,  g_Yl);
    cudaGetSymbolAddress((void**)&hh,  g_hh);  cudaGetSymbolAddress((void**)&hl,  g_hl);
    cudaGetSymbolAddress((void**)&Wh,  g_Winh);cudaGetSymbolAddress((void**)&Wl,  g_Winl);
    cudaGetSymbolAddress((void**)&ih,  g_iph); cudaGetSymbolAddress((void**)&il,  g_ipl);
    cudaGetSymbolAddress((void**)&oh,  g_oph); cudaGetSymbolAddress((void**)&ol,  g_opl);
    cudaGetSymbolAddress((void**)&xph_,g_xph); cudaGetSymbolAddress((void**)&xpl_,g_xpl);
    cudaGetSymbolAddress((void**)&hwh, g_hwh); cudaGetSymbolAddress((void**)&hwl, g_hwl);

    cudaFuncSetAttribute(mma_gemm<0>, cudaFuncAttributeMaxDynamicSharedMemorySize, GSMEM);
    cudaFuncSetAttribute(mma_gemm<1>, cudaFuncAttributeMaxDynamicSharedMemorySize, GSMEM);
    cudaFuncSetAttribute(mma_gemm<2>, cudaFuncAttributeMaxDynamicSharedMemorySize, GSMEM);
    cudaFuncSetAttribute(mma_gemm<3>, cudaFuncAttributeMaxDynamicSharedMemorySize, GSMEM);
    cudaFuncSetAttribute(mma_gemm<4>, cudaFuncAttributeMaxDynamicSharedMemorySize, GSMEM);

    // 0) weight prep + perception split
    prep<<<2304, 256>>>(W_in, in_proj_w, out_proj_w, x_proj_w,
                        mu_w, ls_w, mu_b, ls_b, phb);
    conv_perc<<<4096, 256>>>(perception);

    // 1) x = perc @ W_in^T + b        (8192x256, K=512) -> x planes
    mma_gemm<0><<<dim3(4, 64), 256, GSMEM>>>(
        ph_, pl_, Wh, Wl, P_DIM, P_DIM, nullptr, b_in, nullptr, nullptr, xh, xl);

    // 2) xz = x @ in_proj^T (N=1024)  -> U fp32+planes / Zs fp32
    mma_gemm<1><<<dim3(16, 64), 256, GSMEM>>>(
        xh, xl, ih, il, DM, DM, pU, conv_w, conv_b, pZs, Uh, Ul);

    // 3) x_dbl partials, split-K=2    (K=256 each, lda=512)
    mma_gemm<4><<<dim3(1, 64, 2), 256, GSMEM>>>(
        Uh, Ul, xph_, xpl_, 256, DI, pxd, nullptr, nullptr, nullptr, nullptr, nullptr);

    // 4) pointwise -> Y planes
    mamba_pointwise<<<BATCH / 16, 256>>>(pxd, dt_proj_w, dt_proj_b, Dskip,
                                         pU, pZs, Yh, Yl);

    // 5) h = Y @ out_proj^T           (8192x256, K=512) -> h planes
    mma_gemm<2><<<dim3(4, 64), 256, GSMEM>>>(
        Yh, Yl, oh, ol, DI, DI, nullptr, nullptr, nullptr, nullptr, hh, hl);

    // 6) heads -> out                 (8192x128, K=256)
    mma_gemm<3><<<dim3(2, 64), 256, GSMEM>>>(
        hh, hl, hwh, hwl, DM, DM, nullptr, phb, nullptr, out, nullptr, nullptr);
}